// round 15
// baseline (speedup 1.0000x reference)
#include <cuda_runtime.h>
#include <cuda_fp16.h>
#include <math.h>

#define N_NODES 50000
#define N_EDGES 1600000
#define E_TOT   (N_EDGES + N_NODES)
#define N_PAIRS 2000000
#define N_GRAPHS 50
#define SCAN_BLKS 196   // 196*256 = 50176 >= N_NODES
#define PERSIST_BLKS 1216   // ~8 CTAs/SM: single-wave persistent kernels

#define AS_STRIDE 36    // A smem stride (words): bank=(4r+c)%32 -> conflict-free frags
#define BS_STRIDE 132   // B smem stride: <=2-way frag conflicts

// ---------------- device scratch (static, no runtime alloc) ----------------
__device__ float  g_h384[N_NODES * 384];
__device__ float  g_xl[N_NODES * 128];
__device__ float  g_xr[N_NODES * 128];
__device__ float  g_h2[N_NODES * 128];
__device__ __half g_hbh[N_NODES * 128];      // final LN output, fp16 for pair stage
__device__ int    g_deg[N_NODES];
__device__ int    g_off[N_NODES + 1];
__device__ int    g_cur[N_NODES];
__device__ int    g_csr_src[E_TOT];
__device__ int    g_bsum[SCAN_BLKS];
__device__ int    g_bpre[SCAN_BLKS];
__device__ float  g_stats4[4][2 * N_GRAPHS]; // per-layer: [0:50) sum, [50:100) sumsq
__device__ float  g_gcnt[N_GRAPHS];

__device__ __forceinline__ float lrelu(float x) { return x > 0.f ? x : 0.2f * x; }

__device__ __forceinline__ float ex2(float x) {
    float r;
    asm("ex2.approx.f32 %0, %1;" : "=f"(r) : "f"(x));
    return r;
}

__device__ __forceinline__ unsigned f2tf(float f) {
    unsigned r;
    asm("cvt.rna.tf32.f32 %0, %1;" : "=r"(r) : "f"(f));
    return r;
}

__device__ __forceinline__ void mma1688(float* c, const unsigned* a, const unsigned* b) {
    asm volatile(
        "mma.sync.aligned.m16n8k8.row.col.f32.tf32.tf32.f32 "
        "{%0,%1,%2,%3}, {%4,%5,%6,%7}, {%8,%9}, {%0,%1,%2,%3};"
        : "+f"(c[0]), "+f"(c[1]), "+f"(c[2]), "+f"(c[3])
        : "r"(a[0]), "r"(a[1]), "r"(a[2]), "r"(a[3]), "r"(b[0]), "r"(b[1]));
}

// ---------------- init: zero all accumulators once --------------------------
__global__ void init_kernel() {
    int i = blockIdx.x * blockDim.x + threadIdx.x;
    if (i < N_NODES) g_deg[i] = 0;
    if (i < N_GRAPHS) g_gcnt[i] = 0.f;
    if (i < 4 * 2 * N_GRAPHS) ((float*)g_stats4)[i] = 0.f;
}

// ---------------- time embedding (persistent grid-stride) -------------------
__global__ void embed_kernel(const float* __restrict__ x, const float* __restrict__ t,
                             const float* __restrict__ tW, const float* __restrict__ tb) {
    int tid = threadIdx.x;  // 256
    // node-invariant weights hoisted out of the node loop
    float w1 = tW[tid], w2 = tW[256 + tid], w3 = tW[512 + tid], bb = tb[tid];
    for (int node = blockIdx.x; node < N_NODES; node += gridDim.x) {
        float tv = t[node];
        float s, c;
        __sincosf(tv * 1.57079632679f, &s, &c);
        if (tid < 128)
            g_h384[(size_t)node * 384 + tid] = x[(size_t)node * 128 + tid];
        float te = s * w1 + c * w2 + tv * w3 + bb;
        float sw = te / (1.f + __expf(-te));
        g_h384[(size_t)node * 384 + 128 + tid] = sw;
    }
}

// ---------------- CSR build (+ per-graph node counts fused) ------------------
__global__ void count_kernel(const int* __restrict__ ei, const int* __restrict__ batch) {
    for (int e = blockIdx.x * blockDim.x + threadIdx.x; e < E_TOT; e += gridDim.x * blockDim.x) {
        int d = (e < N_EDGES) ? ei[N_EDGES + e] : (e - N_EDGES);
        atomicAdd(&g_deg[d], 1);
        if (e < N_NODES) atomicAdd(&g_gcnt[batch[e]], 1.0f);
    }
}

__global__ void scan1_kernel() {
    __shared__ int s[256];
    int tid = threadIdx.x;
    int i = blockIdx.x * 256 + tid;
    int d = (i < N_NODES) ? g_deg[i] : 0;
    s[tid] = d;
    __syncthreads();
#pragma unroll
    for (int off = 1; off < 256; off <<= 1) {
        int v = 0;
        if (tid >= off) v = s[tid - off];
        __syncthreads();
        if (tid >= off) s[tid] += v;
        __syncthreads();
    }
    if (i < N_NODES) g_off[i] = s[tid] - d;   // exclusive
    if (tid == 255) g_bsum[blockIdx.x] = s[255];
}

__global__ void scan2_kernel() {
    __shared__ int s[256];
    int tid = threadIdx.x;
    int d = (tid < SCAN_BLKS) ? g_bsum[tid] : 0;
    s[tid] = d;
    __syncthreads();
#pragma unroll
    for (int off = 1; off < 256; off <<= 1) {
        int v = 0;
        if (tid >= off) v = s[tid - off];
        __syncthreads();
        if (tid >= off) s[tid] += v;
        __syncthreads();
    }
    if (tid < SCAN_BLKS) g_bpre[tid] = s[tid] - d;  // exclusive
    if (tid == 0) g_off[N_NODES] = E_TOT;
}

__global__ void scan3_kernel() {
    int i = blockIdx.x * 256 + threadIdx.x;
    if (i < N_NODES) {
        int v = g_off[i] + g_bpre[i >> 8];
        g_off[i] = v;
        g_cur[i] = v;
    }
}

__global__ void scatter_kernel(const int* __restrict__ ei) {
    for (int e = blockIdx.x * blockDim.x + threadIdx.x; e < E_TOT; e += gridDim.x * blockDim.x) {
        int srcv, d;
        if (e < N_EDGES) { srcv = ei[e]; d = ei[N_EDGES + e]; }
        else { srcv = e - N_EDGES; d = srcv; }
        int pos = atomicAdd(&g_cur[d], 1);
        g_csr_src[pos] = srcv;
    }
}

// ---------------- TF32 tensor-core GEMM (R5 config: best measured) ----------
// y[N,128] = A @ W[K,128] + b, A = h or LN(h) elementwise.
// 256 thr = 8 warps (2x4), block tile 128x128, warp tile 64x32, K-chunk 32.
template <bool FUSE_LN>
__global__ __launch_bounds__(256, 2)
void gemm_tc_kernel(const float* __restrict__ h, int K,
                    const float* __restrict__ Wl, const float* __restrict__ bl,
                    const float* __restrict__ Wr, const float* __restrict__ br,
                    float* __restrict__ yl, float* __restrict__ yr,
                    const float* __restrict__ stats, const int* __restrict__ batch,
                    const float* __restrict__ lnw, const float* __restrict__ lnb) {
    __shared__ unsigned As[128 * AS_STRIDE];
    __shared__ unsigned Bs[32 * BS_STRIDE];
    const float* W = (blockIdx.y == 0) ? Wl : Wr;
    const float* bv = (blockIdx.y == 0) ? bl : br;
    float* y = (blockIdx.y == 0) ? yl : yr;

    int t = threadIdx.x;
    int lane = t & 31;
    int wid = t >> 5;
    int wm = wid >> 2;   // 0..1
    int wn = wid & 3;    // 0..3
    int nb = blockIdx.x * 128;

    float acc[4][4][4];
#pragma unroll
    for (int mt = 0; mt < 4; mt++)
#pragma unroll
        for (int nt = 0; nt < 4; nt++)
#pragma unroll
            for (int j = 0; j < 4; j++) acc[mt][nt][j] = 0.f;

    for (int kc = 0; kc < K; kc += 32) {
        // ---- A tile: 128 rows x 32 k ----
#pragma unroll
        for (int it = 0; it < 4; it++) {
            int idx = t + it * 256;       // 0..1023
            int m = idx >> 3;
            int k0 = (idx & 7) * 4;
            int gm = nb + m;
            float4 v = make_float4(0.f, 0.f, 0.f, 0.f);
            if (gm < N_NODES) v = *(const float4*)(h + (size_t)gm * K + kc + k0);
            if (FUSE_LN) {
                int g = batch[gm < N_NODES ? gm : 0];
                float cnt = fmaxf(g_gcnt[g] * 128.f, 1.f);
                float mean = stats[g] / cnt;
                float var = fmaxf(stats[N_GRAPHS + g] / cnt - mean * mean, 0.f);
                float inv = rsqrtf(var + 1e-5f);
                float4 w4 = *(const float4*)(lnw + kc + k0);
                float4 b4 = *(const float4*)(lnb + kc + k0);
                v.x = (v.x - mean) * inv * w4.x + b4.x;
                v.y = (v.y - mean) * inv * w4.y + b4.y;
                v.z = (v.z - mean) * inv * w4.z + b4.z;
                v.w = (v.w - mean) * inv * w4.w + b4.w;
            }
            unsigned* dst = &As[m * AS_STRIDE + k0];
            dst[0] = f2tf(v.x); dst[1] = f2tf(v.y);
            dst[2] = f2tf(v.z); dst[3] = f2tf(v.w);
        }
        // ---- B tile: 32 k x 128 cols ----
#pragma unroll
        for (int it = 0; it < 4; it++) {
            int idx = t + it * 256;
            int k = idx >> 5;
            int n0 = (idx & 31) * 4;
            float4 v = *(const float4*)(W + (size_t)(kc + k) * 128 + n0);
            unsigned* dst = &Bs[k * BS_STRIDE + n0];
            dst[0] = f2tf(v.x); dst[1] = f2tf(v.y);
            dst[2] = f2tf(v.z); dst[3] = f2tf(v.w);
        }
        __syncthreads();
#pragma unroll
        for (int ks = 0; ks < 4; ks++) {
            int k0 = ks * 8;
            unsigned afrag[4][4];
#pragma unroll
            for (int mt = 0; mt < 4; mt++) {
                int row = wm * 64 + mt * 16 + (lane >> 2);
                const unsigned* ap = &As[row * AS_STRIDE + k0 + (lane & 3)];
                afrag[mt][0] = ap[0];
                afrag[mt][1] = ap[8 * AS_STRIDE];
                afrag[mt][2] = ap[4];
                afrag[mt][3] = ap[8 * AS_STRIDE + 4];
            }
            unsigned bfrag[4][2];
#pragma unroll
            for (int nt = 0; nt < 4; nt++) {
                int n = wn * 32 + nt * 8 + (lane >> 2);
                int kk = k0 + (lane & 3);
                bfrag[nt][0] = Bs[kk * BS_STRIDE + n];
                bfrag[nt][1] = Bs[(kk + 4) * BS_STRIDE + n];
            }
#pragma unroll
            for (int mt = 0; mt < 4; mt++)
#pragma unroll
                for (int nt = 0; nt < 4; nt++)
                    mma1688(acc[mt][nt], afrag[mt], bfrag[nt]);
        }
        __syncthreads();
    }
    // ---- epilogue ----
    int gq = lane >> 2, tq = lane & 3;
#pragma unroll
    for (int mt = 0; mt < 4; mt++) {
        int r0 = nb + wm * 64 + mt * 16 + gq;
#pragma unroll
        for (int nt = 0; nt < 4; nt++) {
            int c0 = wn * 32 + nt * 8 + tq * 2;
            float2 bias2 = *(const float2*)(bv + c0);
            if (r0 < N_NODES) {
                float2 o = make_float2(acc[mt][nt][0] + bias2.x, acc[mt][nt][1] + bias2.y);
                *(float2*)(y + (size_t)r0 * 128 + c0) = o;
            }
            if (r0 + 8 < N_NODES) {
                float2 o = make_float2(acc[mt][nt][2] + bias2.x, acc[mt][nt][3] + bias2.y);
                *(float2*)(y + (size_t)(r0 + 8) * 128 + c0) = o;
            }
        }
    }
}

// ---------------- GATv2 aggregation (persistent warp-per-node loop) ---------
// Direct exp-sum softmax (logits provably tiny), ex2-folded att, unrolled x2.
__global__ void agg_kernel(const float* __restrict__ xl, const float* __restrict__ xr,
                           const float* __restrict__ att, const float* __restrict__ bias,
                           const int* __restrict__ batch, float* __restrict__ out,
                           float* __restrict__ stats) {
    int lane = threadIdx.x & 31;
    int warpGlobal = (blockIdx.x * blockDim.x + threadIdx.x) >> 5;
    int totalWarps = (gridDim.x * blockDim.x) >> 5;
    int head = lane >> 3;
    const float LOG2E = 1.44269504088896341f;
    float4 at4 = *(const float4*)(att + head * 32 + (lane & 7) * 4);
    at4.x *= LOG2E; at4.y *= LOG2E; at4.z *= LOG2E; at4.w *= LOG2E;
    float4 b4 = *(const float4*)(bias + lane * 4);

    for (int v = warpGlobal; v < N_NODES; v += totalWarps) {
        float4 xr4 = *(const float4*)(xr + (size_t)v * 128 + lane * 4);
        float4 acc = make_float4(0.f, 0.f, 0.f, 0.f);
        float denom = 0.f;
        int beg = g_off[v], end = g_off[v + 1];

        int p = beg;
        for (; p + 1 < end; p += 2) {
            int s0 = g_csr_src[p];
            int s1 = g_csr_src[p + 1];
            float4 a0 = *(const float4*)(xl + (size_t)s0 * 128 + lane * 4);
            float4 a1 = *(const float4*)(xl + (size_t)s1 * 128 + lane * 4);
            float pt0 = lrelu(a0.x + xr4.x) * at4.x + lrelu(a0.y + xr4.y) * at4.y
                      + lrelu(a0.z + xr4.z) * at4.z + lrelu(a0.w + xr4.w) * at4.w;
            float pt1 = lrelu(a1.x + xr4.x) * at4.x + lrelu(a1.y + xr4.y) * at4.y
                      + lrelu(a1.z + xr4.z) * at4.z + lrelu(a1.w + xr4.w) * at4.w;
            pt0 += __shfl_xor_sync(0xffffffffu, pt0, 1);
            pt1 += __shfl_xor_sync(0xffffffffu, pt1, 1);
            pt0 += __shfl_xor_sync(0xffffffffu, pt0, 2);
            pt1 += __shfl_xor_sync(0xffffffffu, pt1, 2);
            pt0 += __shfl_xor_sync(0xffffffffu, pt0, 4);
            pt1 += __shfl_xor_sync(0xffffffffu, pt1, 4);
            float w0 = ex2(pt0);
            float w1 = ex2(pt1);
            denom += w0 + w1;
            acc.x += w0 * a0.x + w1 * a1.x;
            acc.y += w0 * a0.y + w1 * a1.y;
            acc.z += w0 * a0.z + w1 * a1.z;
            acc.w += w0 * a0.w + w1 * a1.w;
        }
        if (p < end) {
            int s0 = g_csr_src[p];
            float4 a0 = *(const float4*)(xl + (size_t)s0 * 128 + lane * 4);
            float pt0 = lrelu(a0.x + xr4.x) * at4.x + lrelu(a0.y + xr4.y) * at4.y
                      + lrelu(a0.z + xr4.z) * at4.z + lrelu(a0.w + xr4.w) * at4.w;
            pt0 += __shfl_xor_sync(0xffffffffu, pt0, 1);
            pt0 += __shfl_xor_sync(0xffffffffu, pt0, 2);
            pt0 += __shfl_xor_sync(0xffffffffu, pt0, 4);
            float w0 = ex2(pt0);
            denom += w0;
            acc.x += w0 * a0.x;
            acc.y += w0 * a0.y;
            acc.z += w0 * a0.z;
            acc.w += w0 * a0.w;
        }
        float inv = 1.f / (denom + 1e-16f);
        float4 o;
        o.x = acc.x * inv + b4.x;
        o.y = acc.y * inv + b4.y;
        o.z = acc.z * inv + b4.z;
        o.w = acc.w * inv + b4.w;
        *(float4*)(out + (size_t)v * 128 + lane * 4) = o;
        float s1 = o.x + o.y + o.z + o.w;
        float q1 = o.x * o.x + o.y * o.y + o.z * o.z + o.w * o.w;
#pragma unroll
        for (int off = 16; off > 0; off >>= 1) {
            s1 += __shfl_xor_sync(0xffffffffu, s1, off);
            q1 += __shfl_xor_sync(0xffffffffu, q1, off);
        }
        if (lane == 0) {
            int g = batch[v];
            atomicAdd(&stats[g], s1);
            atomicAdd(&stats[N_GRAPHS + g], q1);
        }
    }
}

// ---------------- final graph layernorm apply -> fp16 (grid-stride) ---------
__global__ void ln_apply_h_kernel(const float* __restrict__ h, const int* __restrict__ batch,
                                  const float* __restrict__ w, const float* __restrict__ b,
                                  __half* __restrict__ out, const float* __restrict__ stats) {
    for (int idx = blockIdx.x * blockDim.x + threadIdx.x; idx < N_NODES * 32;
         idx += gridDim.x * blockDim.x) {
        int node = idx >> 5;
        int c4 = idx & 31;
        int g = batch[node];
        float cnt = fmaxf(g_gcnt[g] * 128.f, 1.f);
        float mean = stats[g] / cnt;
        float var = fmaxf(stats[N_GRAPHS + g] / cnt - mean * mean, 0.f);
        float inv = rsqrtf(var + 1e-5f);
        float4 hv = *(const float4*)(h + (size_t)node * 128 + c4 * 4);
        float4 w4 = ((const float4*)w)[c4];
        float4 b4 = ((const float4*)b)[c4];
        float ox = (hv.x - mean) * inv * w4.x + b4.x;
        float oy = (hv.y - mean) * inv * w4.y + b4.y;
        float oz = (hv.z - mean) * inv * w4.z + b4.z;
        float ow = (hv.w - mean) * inv * w4.w + b4.w;
        *(__half2*)(out + (size_t)node * 128 + c4 * 4) = __floats2half2_rn(ox, oy);
        *(__half2*)(out + (size_t)node * 128 + c4 * 4 + 2) = __floats2half2_rn(oz, ow);
    }
}

// ---------------- pair scoring: 2 pairs/warp, persistent grid-stride --------
__global__ void pair_kernel(const __half* __restrict__ h, const int* __restrict__ pidx,
                            const float* __restrict__ linkW, const float* __restrict__ linkb,
                            float* __restrict__ out) {
    int lane = threadIdx.x & 31;
    int half = lane >> 4;         // which pair within the warp
    int sub  = lane & 15;         // lane within the 16-lane group
    int warpGlobal = (blockIdx.x * blockDim.x + threadIdx.x) >> 5;
    int totalWarps = (gridDim.x * blockDim.x) >> 5;
    float4 lw0 = ((const float4*)linkW)[sub * 2];
    float4 lw1 = ((const float4*)linkW)[sub * 2 + 1];
    float lb = linkb[0];

    for (int pw = warpGlobal * 2 + half; pw < N_PAIRS; pw += totalWarps * 2) {
        int a = pidx[pw];
        int bnode = pidx[N_PAIRS + pw];
        uint4 ua = *(const uint4*)(h + (size_t)a * 128 + sub * 8);
        uint4 ub = *(const uint4*)(h + (size_t)bnode * 128 + sub * 8);
        float2 a0 = __half22float2(*(__half2*)&ua.x);
        float2 a1 = __half22float2(*(__half2*)&ua.y);
        float2 a2 = __half22float2(*(__half2*)&ua.z);
        float2 a3 = __half22float2(*(__half2*)&ua.w);
        float2 b0 = __half22float2(*(__half2*)&ub.x);
        float2 b1 = __half22float2(*(__half2*)&ub.y);
        float2 b2 = __half22float2(*(__half2*)&ub.z);
        float2 b3 = __half22float2(*(__half2*)&ub.w);
        float d = a0.x * b0.x * lw0.x + a0.y * b0.y * lw0.y
                + a1.x * b1.x * lw0.z + a1.y * b1.y * lw0.w
                + a2.x * b2.x * lw1.x + a2.y * b2.y * lw1.y
                + a3.x * b3.x * lw1.z + a3.y * b3.y * lw1.w;
#pragma unroll
        for (int o = 8; o > 0; o >>= 1) d += __shfl_xor_sync(0xffffffffu, d, o);
        if (sub == 0) {
            float z = d + lb;
            out[pw] = 1.f / (1.f + __expf(-z));
        }
    }
}

// ---------------- host orchestration (single stream) -------------------------
extern "C" void kernel_launch(void* const* d_in, const int* in_sizes, int n_in,
                              void* d_out, int out_size) {
    const float* x     = (const float*)d_in[0];
    const float* t     = (const float*)d_in[1];
    const int*   ei    = (const int*)d_in[2];
    const int*   pidx  = (const int*)d_in[3];
    const int*   batch = (const int*)d_in[4];
    const float* tW    = (const float*)d_in[5];
    const float* tb    = (const float*)d_in[6];
    const float* W0l   = (const float*)d_in[7];
    const float* b0l   = (const float*)d_in[8];
    const float* W0r   = (const float*)d_in[9];
    const float* b0r   = (const float*)d_in[10];
    const float* att0  = (const float*)d_in[11];
    const float* bias0 = (const float*)d_in[12];
    const float* Wl    = (const float*)d_in[13];
    const float* bl    = (const float*)d_in[14];
    const float* Wr    = (const float*)d_in[15];
    const float* br    = (const float*)d_in[16];
    const float* att   = (const float*)d_in[17];
    const float* bias  = (const float*)d_in[18];
    const float* lnw   = (const float*)d_in[19];
    const float* lnb   = (const float*)d_in[20];
    const float* linkW = (const float*)d_in[21];
    const float* linkb = (const float*)d_in[22];
    float* out = (float*)d_out;

    float *p_h384, *p_xl, *p_xr, *p_h2, *p_stats;
    __half* p_hbh;
    cudaGetSymbolAddress((void**)&p_h384, g_h384);
    cudaGetSymbolAddress((void**)&p_xl, g_xl);
    cudaGetSymbolAddress((void**)&p_xr, g_xr);
    cudaGetSymbolAddress((void**)&p_h2, g_h2);
    cudaGetSymbolAddress((void**)&p_hbh, g_hbh);
    cudaGetSymbolAddress((void**)&p_stats, g_stats4);

    const int GEMM_BLKS = (N_NODES + 127) / 128;
    dim3 ggrid(GEMM_BLKS, 2);

    // single stream; layer-0 GEMM kept as 4th launch for ncu visibility
    init_kernel<<<SCAN_BLKS, 256>>>();                                 // 1
    embed_kernel<<<PERSIST_BLKS, 256>>>(x, t, tW, tb);                 // 2
    count_kernel<<<(E_TOT + 1023) / 1024, 256>>>(ei, batch);           // 3
    gemm_tc_kernel<false><<<ggrid, 256>>>(p_h384, 384, W0l, b0l, W0r, b0r,
                                          p_xl, p_xr, nullptr, batch, nullptr, nullptr); // 4
    scan1_kernel<<<SCAN_BLKS, 256>>>();                                // 5
    scan2_kernel<<<1, 256>>>();                                        // 6
    scan3_kernel<<<SCAN_BLKS, 256>>>();                                // 7
    scatter_kernel<<<(E_TOT + 1023) / 1024, 256>>>(ei);                // 8

    // --- layer 0 aggregation ---
    agg_kernel<<<PERSIST_BLKS, 256>>>(p_xl, p_xr, att0, bias0, batch, p_h2, p_stats);

    // --- layers 1..3: LN fused into GEMM A-load ---
    for (int i = 0; i < 3; i++) {
        const float* Wli = Wl + (size_t)i * 128 * 128;
        const float* bli = bl + (size_t)i * 128;
        const float* Wri = Wr + (size_t)i * 128 * 128;
        const float* bri = br + (size_t)i * 128;
        const float* ai  = att + (size_t)i * 128;
        const float* bi  = bias + (size_t)i * 128;
        const float* st_prev = p_stats + (size_t)i * 2 * N_GRAPHS;
        float* st = p_stats + (size_t)(i + 1) * 2 * N_GRAPHS;
        gemm_tc_kernel<true><<<ggrid, 256>>>(p_h2, 128, Wli, bli, Wri, bri,
                                             p_xl, p_xr, st_prev, batch,
                                             lnw + (size_t)i * 128, lnb + (size_t)i * 128);
        agg_kernel<<<PERSIST_BLKS, 256>>>(p_xl, p_xr, ai, bi, batch, p_h2, st);
    }

    // final LN (fp16 output) + pair scoring (persistent)
    ln_apply_h_kernel<<<PERSIST_BLKS, 256>>>(p_h2, batch, lnw + 3 * 128, lnb + 3 * 128,
                                             p_hbh, p_stats + 3 * 2 * N_GRAPHS);
    pair_kernel<<<PERSIST_BLKS, 256>>>(p_hbh, pidx, linkW, linkb, out);
    (void)in_sizes; (void)n_in; (void)out_size;
}

// round 16
// speedup vs baseline: 1.0423x; 1.0423x over previous
#include <cuda_runtime.h>
#include <cuda_fp16.h>
#include <math.h>

#define N_NODES 50000
#define N_EDGES 1600000
#define E_TOT   (N_EDGES + N_NODES)
#define N_PAIRS 2000000
#define N_GRAPHS 50
#define SCAN_BLKS 196      // 196*256 = 50176 >= N_NODES
#define EMBED_BLKS 608
#define COUNT_BLKS 608
#define SCAT_BLKS  608
#define GEMM_BLKS  391     // ceil(50000/128)

#define AS_STRIDE 36    // A smem stride (words): bank=(4r+c)%32 -> conflict-free frags
#define BS_STRIDE 132   // B smem stride: <=2-way frag conflicts

// ---------------- device scratch (static, no runtime alloc) ----------------
__device__ float  g_h384[N_NODES * 384];
__device__ float  g_xl[N_NODES * 128];
__device__ float  g_xr[N_NODES * 128];
__device__ float  g_h2[N_NODES * 128];
__device__ __half g_hbh[N_NODES * 128];      // final LN output, fp16 for pair stage
__device__ int    g_deg[N_NODES];
__device__ int    g_off[N_NODES + 1];
__device__ int    g_cur[N_NODES];
__device__ int    g_csr_src[E_TOT];
__device__ int    g_bsum[SCAN_BLKS];
__device__ int    g_bpre[SCAN_BLKS];
__device__ float  g_stats4[4][2 * N_GRAPHS]; // per-layer: [0:50) sum, [50:100) sumsq
__device__ float  g_gcnt[N_GRAPHS];

__device__ __forceinline__ float lrelu(float x) { return x > 0.f ? x : 0.2f * x; }

__device__ __forceinline__ float ex2(float x) {
    float r;
    asm("ex2.approx.f32 %0, %1;" : "=f"(r) : "f"(x));
    return r;
}

__device__ __forceinline__ unsigned f2tf(float f) {
    unsigned r;
    asm("cvt.rna.tf32.f32 %0, %1;" : "=r"(r) : "f"(f));
    return r;
}

__device__ __forceinline__ void mma1688(float* c, const unsigned* a, const unsigned* b) {
    asm volatile(
        "mma.sync.aligned.m16n8k8.row.col.f32.tf32.tf32.f32 "
        "{%0,%1,%2,%3}, {%4,%5,%6,%7}, {%8,%9}, {%0,%1,%2,%3};"
        : "+f"(c[0]), "+f"(c[1]), "+f"(c[2]), "+f"(c[3])
        : "r"(a[0]), "r"(a[1]), "r"(a[2]), "r"(a[3]), "r"(b[0]), "r"(b[1]));
}

// ---------------- init: zero all accumulators once --------------------------
__global__ void init_kernel() {
    int i = blockIdx.x * blockDim.x + threadIdx.x;
    if (i < N_NODES) g_deg[i] = 0;
    if (i < N_GRAPHS) g_gcnt[i] = 0.f;
    if (i < 4 * 2 * N_GRAPHS) ((float*)g_stats4)[i] = 0.f;
}

// ---------------- fused: embed (blocks [0,608)) || count (blocks [608,1216)) -
__global__ void fused_embed_count(const float* __restrict__ x, const float* __restrict__ t,
                                  const float* __restrict__ tW, const float* __restrict__ tb,
                                  const int* __restrict__ ei, const int* __restrict__ batch) {
    int b = blockIdx.x;
    int tid = threadIdx.x;
    if (b < EMBED_BLKS) {
        // embed path: persistent over nodes
        float w1 = tW[tid], w2 = tW[256 + tid], w3 = tW[512 + tid], bb = tb[tid];
        for (int node = b; node < N_NODES; node += EMBED_BLKS) {
            float tv = t[node];
            float s, c;
            __sincosf(tv * 1.57079632679f, &s, &c);
            if (tid < 128)
                g_h384[(size_t)node * 384 + tid] = x[(size_t)node * 128 + tid];
            float te = s * w1 + c * w2 + tv * w3 + bb;
            float sw = te / (1.f + __expf(-te));
            g_h384[(size_t)node * 384 + 128 + tid] = sw;
        }
    } else {
        // count path (+ per-graph node counts)
        int vb = b - EMBED_BLKS;
        for (int e = vb * 256 + tid; e < E_TOT; e += COUNT_BLKS * 256) {
            int d = (e < N_EDGES) ? ei[N_EDGES + e] : (e - N_EDGES);
            atomicAdd(&g_deg[d], 1);
            if (e < N_NODES) atomicAdd(&g_gcnt[batch[e]], 1.0f);
        }
    }
}

__global__ void scan1_kernel() {
    __shared__ int s[256];
    int tid = threadIdx.x;
    int i = blockIdx.x * 256 + tid;
    int d = (i < N_NODES) ? g_deg[i] : 0;
    s[tid] = d;
    __syncthreads();
#pragma unroll
    for (int off = 1; off < 256; off <<= 1) {
        int v = 0;
        if (tid >= off) v = s[tid - off];
        __syncthreads();
        if (tid >= off) s[tid] += v;
        __syncthreads();
    }
    if (i < N_NODES) g_off[i] = s[tid] - d;   // exclusive
    if (tid == 255) g_bsum[blockIdx.x] = s[255];
}

__global__ void scan2_kernel() {
    __shared__ int s[256];
    int tid = threadIdx.x;
    int d = (tid < SCAN_BLKS) ? g_bsum[tid] : 0;
    s[tid] = d;
    __syncthreads();
#pragma unroll
    for (int off = 1; off < 256; off <<= 1) {
        int v = 0;
        if (tid >= off) v = s[tid - off];
        __syncthreads();
        if (tid >= off) s[tid] += v;
        __syncthreads();
    }
    if (tid < SCAN_BLKS) g_bpre[tid] = s[tid] - d;  // exclusive
    if (tid == 0) g_off[N_NODES] = E_TOT;
}

__global__ void scan3_kernel() {
    int i = blockIdx.x * 256 + threadIdx.x;
    if (i < N_NODES) {
        int v = g_off[i] + g_bpre[i >> 8];
        g_off[i] = v;
        g_cur[i] = v;
    }
}

// ---------------- fused: gemm0 (blocks [0,782)) || scatter ([782,1390)) ------
// gemm: TF32 tensor-core, R5 config. b&1 selects l/r, b>>1 selects node tile.
__global__ __launch_bounds__(256, 2)
void fused_gemm0_scatter(const float* __restrict__ h,
                         const float* __restrict__ Wl, const float* __restrict__ bl,
                         const float* __restrict__ Wr, const float* __restrict__ br,
                         float* __restrict__ yl, float* __restrict__ yr,
                         const int* __restrict__ ei) {
    __shared__ unsigned As[128 * AS_STRIDE];
    __shared__ unsigned Bs[32 * BS_STRIDE];
    int b = blockIdx.x;
    int t = threadIdx.x;
    const int K = 384;

    if (b >= 2 * GEMM_BLKS) {
        // ---- scatter path ----
        int vb = b - 2 * GEMM_BLKS;
        for (int e = vb * 256 + t; e < E_TOT; e += SCAT_BLKS * 256) {
            int srcv, d;
            if (e < N_EDGES) { srcv = ei[e]; d = ei[N_EDGES + e]; }
            else { srcv = e - N_EDGES; d = srcv; }
            int pos = atomicAdd(&g_cur[d], 1);
            g_csr_src[pos] = srcv;
        }
        return;
    }

    // ---- gemm path ----
    int by = b & 1;
    int bx = b >> 1;
    const float* W = (by == 0) ? Wl : Wr;
    const float* bv = (by == 0) ? bl : br;
    float* y = (by == 0) ? yl : yr;

    int lane = t & 31;
    int wid = t >> 5;
    int wm = wid >> 2;   // 0..1
    int wn = wid & 3;    // 0..3
    int nb = bx * 128;

    float acc[4][4][4];
#pragma unroll
    for (int mt = 0; mt < 4; mt++)
#pragma unroll
        for (int nt = 0; nt < 4; nt++)
#pragma unroll
            for (int j = 0; j < 4; j++) acc[mt][nt][j] = 0.f;

    for (int kc = 0; kc < K; kc += 32) {
#pragma unroll
        for (int it = 0; it < 4; it++) {
            int idx = t + it * 256;
            int m = idx >> 3;
            int k0 = (idx & 7) * 4;
            int gm = nb + m;
            float4 v = make_float4(0.f, 0.f, 0.f, 0.f);
            if (gm < N_NODES) v = *(const float4*)(h + (size_t)gm * K + kc + k0);
            unsigned* dst = &As[m * AS_STRIDE + k0];
            dst[0] = f2tf(v.x); dst[1] = f2tf(v.y);
            dst[2] = f2tf(v.z); dst[3] = f2tf(v.w);
        }
#pragma unroll
        for (int it = 0; it < 4; it++) {
            int idx = t + it * 256;
            int k = idx >> 5;
            int n0 = (idx & 31) * 4;
            float4 v = *(const float4*)(W + (size_t)(kc + k) * 128 + n0);
            unsigned* dst = &Bs[k * BS_STRIDE + n0];
            dst[0] = f2tf(v.x); dst[1] = f2tf(v.y);
            dst[2] = f2tf(v.z); dst[3] = f2tf(v.w);
        }
        __syncthreads();
#pragma unroll
        for (int ks = 0; ks < 4; ks++) {
            int k0 = ks * 8;
            unsigned afrag[4][4];
#pragma unroll
            for (int mt = 0; mt < 4; mt++) {
                int row = wm * 64 + mt * 16 + (lane >> 2);
                const unsigned* ap = &As[row * AS_STRIDE + k0 + (lane & 3)];
                afrag[mt][0] = ap[0];
                afrag[mt][1] = ap[8 * AS_STRIDE];
                afrag[mt][2] = ap[4];
                afrag[mt][3] = ap[8 * AS_STRIDE + 4];
            }
            unsigned bfrag[4][2];
#pragma unroll
            for (int nt = 0; nt < 4; nt++) {
                int n = wn * 32 + nt * 8 + (lane >> 2);
                int kk = k0 + (lane & 3);
                bfrag[nt][0] = Bs[kk * BS_STRIDE + n];
                bfrag[nt][1] = Bs[(kk + 4) * BS_STRIDE + n];
            }
#pragma unroll
            for (int mt = 0; mt < 4; mt++)
#pragma unroll
                for (int nt = 0; nt < 4; nt++)
                    mma1688(acc[mt][nt], afrag[mt], bfrag[nt]);
        }
        __syncthreads();
    }
    int gq = lane >> 2, tq = lane & 3;
#pragma unroll
    for (int mt = 0; mt < 4; mt++) {
        int r0 = nb + wm * 64 + mt * 16 + gq;
#pragma unroll
        for (int nt = 0; nt < 4; nt++) {
            int c0 = wn * 32 + nt * 8 + tq * 2;
            float2 bias2 = *(const float2*)(bv + c0);
            if (r0 < N_NODES) {
                float2 o = make_float2(acc[mt][nt][0] + bias2.x, acc[mt][nt][1] + bias2.y);
                *(float2*)(y + (size_t)r0 * 128 + c0) = o;
            }
            if (r0 + 8 < N_NODES) {
                float2 o = make_float2(acc[mt][nt][2] + bias2.x, acc[mt][nt][3] + bias2.y);
                *(float2*)(y + (size_t)(r0 + 8) * 128 + c0) = o;
            }
        }
    }
}

// ---------------- TF32 tensor-core GEMM with fused LN (layers 1..3) ---------
__global__ __launch_bounds__(256, 2)
void gemm_tc_ln_kernel(const float* __restrict__ h,
                       const float* __restrict__ Wl, const float* __restrict__ bl,
                       const float* __restrict__ Wr, const float* __restrict__ br,
                       float* __restrict__ yl, float* __restrict__ yr,
                       const float* __restrict__ stats, const int* __restrict__ batch,
                       const float* __restrict__ lnw, const float* __restrict__ lnb) {
    __shared__ unsigned As[128 * AS_STRIDE];
    __shared__ unsigned Bs[32 * BS_STRIDE];
    const int K = 128;
    const float* W = (blockIdx.y == 0) ? Wl : Wr;
    const float* bv = (blockIdx.y == 0) ? bl : br;
    float* y = (blockIdx.y == 0) ? yl : yr;

    int t = threadIdx.x;
    int lane = t & 31;
    int wid = t >> 5;
    int wm = wid >> 2;
    int wn = wid & 3;
    int nb = blockIdx.x * 128;

    float acc[4][4][4];
#pragma unroll
    for (int mt = 0; mt < 4; mt++)
#pragma unroll
        for (int nt = 0; nt < 4; nt++)
#pragma unroll
            for (int j = 0; j < 4; j++) acc[mt][nt][j] = 0.f;

    for (int kc = 0; kc < K; kc += 32) {
#pragma unroll
        for (int it = 0; it < 4; it++) {
            int idx = t + it * 256;
            int m = idx >> 3;
            int k0 = (idx & 7) * 4;
            int gm = nb + m;
            float4 v = make_float4(0.f, 0.f, 0.f, 0.f);
            if (gm < N_NODES) v = *(const float4*)(h + (size_t)gm * K + kc + k0);
            int g = batch[gm < N_NODES ? gm : 0];
            float cnt = fmaxf(g_gcnt[g] * 128.f, 1.f);
            float mean = stats[g] / cnt;
            float var = fmaxf(stats[N_GRAPHS + g] / cnt - mean * mean, 0.f);
            float inv = rsqrtf(var + 1e-5f);
            float4 w4 = *(const float4*)(lnw + kc + k0);
            float4 b4 = *(const float4*)(lnb + kc + k0);
            v.x = (v.x - mean) * inv * w4.x + b4.x;
            v.y = (v.y - mean) * inv * w4.y + b4.y;
            v.z = (v.z - mean) * inv * w4.z + b4.z;
            v.w = (v.w - mean) * inv * w4.w + b4.w;
            unsigned* dst = &As[m * AS_STRIDE + k0];
            dst[0] = f2tf(v.x); dst[1] = f2tf(v.y);
            dst[2] = f2tf(v.z); dst[3] = f2tf(v.w);
        }
#pragma unroll
        for (int it = 0; it < 4; it++) {
            int idx = t + it * 256;
            int k = idx >> 5;
            int n0 = (idx & 31) * 4;
            float4 v = *(const float4*)(W + (size_t)(kc + k) * 128 + n0);
            unsigned* dst = &Bs[k * BS_STRIDE + n0];
            dst[0] = f2tf(v.x); dst[1] = f2tf(v.y);
            dst[2] = f2tf(v.z); dst[3] = f2tf(v.w);
        }
        __syncthreads();
#pragma unroll
        for (int ks = 0; ks < 4; ks++) {
            int k0 = ks * 8;
            unsigned afrag[4][4];
#pragma unroll
            for (int mt = 0; mt < 4; mt++) {
                int row = wm * 64 + mt * 16 + (lane >> 2);
                const unsigned* ap = &As[row * AS_STRIDE + k0 + (lane & 3)];
                afrag[mt][0] = ap[0];
                afrag[mt][1] = ap[8 * AS_STRIDE];
                afrag[mt][2] = ap[4];
                afrag[mt][3] = ap[8 * AS_STRIDE + 4];
            }
            unsigned bfrag[4][2];
#pragma unroll
            for (int nt = 0; nt < 4; nt++) {
                int n = wn * 32 + nt * 8 + (lane >> 2);
                int kk = k0 + (lane & 3);
                bfrag[nt][0] = Bs[kk * BS_STRIDE + n];
                bfrag[nt][1] = Bs[(kk + 4) * BS_STRIDE + n];
            }
#pragma unroll
            for (int mt = 0; mt < 4; mt++)
#pragma unroll
                for (int nt = 0; nt < 4; nt++)
                    mma1688(acc[mt][nt], afrag[mt], bfrag[nt]);
        }
        __syncthreads();
    }
    int gq = lane >> 2, tq = lane & 3;
#pragma unroll
    for (int mt = 0; mt < 4; mt++) {
        int r0 = nb + wm * 64 + mt * 16 + gq;
#pragma unroll
        for (int nt = 0; nt < 4; nt++) {
            int c0 = wn * 32 + nt * 8 + tq * 2;
            float2 bias2 = *(const float2*)(bv + c0);
            if (r0 < N_NODES) {
                float2 o = make_float2(acc[mt][nt][0] + bias2.x, acc[mt][nt][1] + bias2.y);
                *(float2*)(y + (size_t)r0 * 128 + c0) = o;
            }
            if (r0 + 8 < N_NODES) {
                float2 o = make_float2(acc[mt][nt][2] + bias2.x, acc[mt][nt][3] + bias2.y);
                *(float2*)(y + (size_t)(r0 + 8) * 128 + c0) = o;
            }
        }
    }
}

// ---------------- GATv2 aggregation (R14-exact: best measured) --------------
__global__ void agg_kernel(const float* __restrict__ xl, const float* __restrict__ xr,
                           const float* __restrict__ att, const float* __restrict__ bias,
                           const int* __restrict__ batch, float* __restrict__ out,
                           float* __restrict__ stats) {
    int v = (blockIdx.x * blockDim.x + threadIdx.x) >> 5;
    int lane = threadIdx.x & 31;
    if (v >= N_NODES) return;
    int head = lane >> 3;
    float4 xr4 = *(const float4*)(xr + (size_t)v * 128 + lane * 4);
    float4 at4 = *(const float4*)(att + head * 32 + (lane & 7) * 4);
    const float LOG2E = 1.44269504088896341f;
    at4.x *= LOG2E; at4.y *= LOG2E; at4.z *= LOG2E; at4.w *= LOG2E;
    float4 acc = make_float4(0.f, 0.f, 0.f, 0.f);
    float denom = 0.f;
    int beg = g_off[v], end = g_off[v + 1];

    int p = beg;
    for (; p + 1 < end; p += 2) {
        int s0 = g_csr_src[p];
        int s1 = g_csr_src[p + 1];
        float4 a0 = *(const float4*)(xl + (size_t)s0 * 128 + lane * 4);
        float4 a1 = *(const float4*)(xl + (size_t)s1 * 128 + lane * 4);
        float pt0 = lrelu(a0.x + xr4.x) * at4.x + lrelu(a0.y + xr4.y) * at4.y
                  + lrelu(a0.z + xr4.z) * at4.z + lrelu(a0.w + xr4.w) * at4.w;
        float pt1 = lrelu(a1.x + xr4.x) * at4.x + lrelu(a1.y + xr4.y) * at4.y
                  + lrelu(a1.z + xr4.z) * at4.z + lrelu(a1.w + xr4.w) * at4.w;
        pt0 += __shfl_xor_sync(0xffffffffu, pt0, 1);
        pt1 += __shfl_xor_sync(0xffffffffu, pt1, 1);
        pt0 += __shfl_xor_sync(0xffffffffu, pt0, 2);
        pt1 += __shfl_xor_sync(0xffffffffu, pt1, 2);
        pt0 += __shfl_xor_sync(0xffffffffu, pt0, 4);
        pt1 += __shfl_xor_sync(0xffffffffu, pt1, 4);
        float w0 = ex2(pt0);
        float w1 = ex2(pt1);
        denom += w0 + w1;
        acc.x += w0 * a0.x + w1 * a1.x;
        acc.y += w0 * a0.y + w1 * a1.y;
        acc.z += w0 * a0.z + w1 * a1.z;
        acc.w += w0 * a0.w + w1 * a1.w;
    }
    if (p < end) {
        int s0 = g_csr_src[p];
        float4 a0 = *(const float4*)(xl + (size_t)s0 * 128 + lane * 4);
        float pt0 = lrelu(a0.x + xr4.x) * at4.x + lrelu(a0.y + xr4.y) * at4.y
                  + lrelu(a0.z + xr4.z) * at4.z + lrelu(a0.w + xr4.w) * at4.w;
        pt0 += __shfl_xor_sync(0xffffffffu, pt0, 1);
        pt0 += __shfl_xor_sync(0xffffffffu, pt0, 2);
        pt0 += __shfl_xor_sync(0xffffffffu, pt0, 4);
        float w0 = ex2(pt0);
        denom += w0;
        acc.x += w0 * a0.x;
        acc.y += w0 * a0.y;
        acc.z += w0 * a0.z;
        acc.w += w0 * a0.w;
    }
    float inv = 1.f / (denom + 1e-16f);
    float4 b4 = *(const float4*)(bias + lane * 4);
    float4 o;
    o.x = acc.x * inv + b4.x;
    o.y = acc.y * inv + b4.y;
    o.z = acc.z * inv + b4.z;
    o.w = acc.w * inv + b4.w;
    *(float4*)(out + (size_t)v * 128 + lane * 4) = o;
    float s1 = o.x + o.y + o.z + o.w;
    float q1 = o.x * o.x + o.y * o.y + o.z * o.z + o.w * o.w;
#pragma unroll
    for (int off = 16; off > 0; off >>= 1) {
        s1 += __shfl_xor_sync(0xffffffffu, s1, off);
        q1 += __shfl_xor_sync(0xffffffffu, q1, off);
    }
    if (lane == 0) {
        int g = batch[v];
        atomicAdd(&stats[g], s1);
        atomicAdd(&stats[N_GRAPHS + g], q1);
    }
}

// ---------------- final graph layernorm apply -> fp16 packed -----------------
__global__ void ln_apply_h_kernel(const float* __restrict__ h, const int* __restrict__ batch,
                                  const float* __restrict__ w, const float* __restrict__ b,
                                  __half* __restrict__ out, const float* __restrict__ stats) {
    int idx = blockIdx.x * blockDim.x + threadIdx.x;
    if (idx >= N_NODES * 32) return;
    int node = idx >> 5;
    int c4 = idx & 31;
    int g = batch[node];
    float cnt = fmaxf(g_gcnt[g] * 128.f, 1.f);
    float mean = stats[g] / cnt;
    float var = fmaxf(stats[N_GRAPHS + g] / cnt - mean * mean, 0.f);
    float inv = rsqrtf(var + 1e-5f);
    float4 hv = *(const float4*)(h + (size_t)node * 128 + c4 * 4);
    float4 w4 = ((const float4*)w)[c4];
    float4 b4 = ((const float4*)b)[c4];
    float ox = (hv.x - mean) * inv * w4.x + b4.x;
    float oy = (hv.y - mean) * inv * w4.y + b4.y;
    float oz = (hv.z - mean) * inv * w4.z + b4.z;
    float ow = (hv.w - mean) * inv * w4.w + b4.w;
    *(__half2*)(out + (size_t)node * 128 + c4 * 4) = __floats2half2_rn(ox, oy);
    *(__half2*)(out + (size_t)node * 128 + c4 * 4 + 2) = __floats2half2_rn(oz, ow);
}

// ---------------- pair scoring: 2 pairs per warp (R12-exact) -----------------
__global__ void pair_kernel(const __half* __restrict__ h, const int* __restrict__ pidx,
                            const float* __restrict__ linkW, const float* __restrict__ linkb,
                            float* __restrict__ out) {
    int warp = (blockIdx.x * blockDim.x + threadIdx.x) >> 5;
    int lane = threadIdx.x & 31;
    int half = lane >> 4;
    int sub  = lane & 15;
    int pw = warp * 2 + half;
    if (pw >= N_PAIRS) return;
    int a = pidx[pw];
    int bnode = pidx[N_PAIRS + pw];
    uint4 ua = *(const uint4*)(h + (size_t)a * 128 + sub * 8);
    uint4 ub = *(const uint4*)(h + (size_t)bnode * 128 + sub * 8);
    float2 a0 = __half22float2(*(__half2*)&ua.x);
    float2 a1 = __half22float2(*(__half2*)&ua.y);
    float2 a2 = __half22float2(*(__half2*)&ua.z);
    float2 a3 = __half22float2(*(__half2*)&ua.w);
    float2 b0 = __half22float2(*(__half2*)&ub.x);
    float2 b1 = __half22float2(*(__half2*)&ub.y);
    float2 b2 = __half22float2(*(__half2*)&ub.z);
    float2 b3 = __half22float2(*(__half2*)&ub.w);
    float4 lw0 = ((const float4*)linkW)[sub * 2];
    float4 lw1 = ((const float4*)linkW)[sub * 2 + 1];
    float d = a0.x * b0.x * lw0.x + a0.y * b0.y * lw0.y
            + a1.x * b1.x * lw0.z + a1.y * b1.y * lw0.w
            + a2.x * b2.x * lw1.x + a2.y * b2.y * lw1.y
            + a3.x * b3.x * lw1.z + a3.y * b3.y * lw1.w;
#pragma unroll
    for (int o = 8; o > 0; o >>= 1) d += __shfl_xor_sync(0xffffffffu, d, o);
    if (sub == 0) {
        float z = d + linkb[0];
        out[pw] = 1.f / (1.f + __expf(-z));
    }
}

// ---------------- host orchestration (single stream) -------------------------
extern "C" void kernel_launch(void* const* d_in, const int* in_sizes, int n_in,
                              void* d_out, int out_size) {
    const float* x     = (const float*)d_in[0];
    const float* t     = (const float*)d_in[1];
    const int*   ei    = (const int*)d_in[2];
    const int*   pidx  = (const int*)d_in[3];
    const int*   batch = (const int*)d_in[4];
    const float* tW    = (const float*)d_in[5];
    const float* tb    = (const float*)d_in[6];
    const float* W0l   = (const float*)d_in[7];
    const float* b0l   = (const float*)d_in[8];
    const float* W0r   = (const float*)d_in[9];
    const float* b0r   = (const float*)d_in[10];
    const float* att0  = (const float*)d_in[11];
    const float* bias0 = (const float*)d_in[12];
    const float* Wl    = (const float*)d_in[13];
    const float* bl    = (const float*)d_in[14];
    const float* Wr    = (const float*)d_in[15];
    const float* br    = (const float*)d_in[16];
    const float* att   = (const float*)d_in[17];
    const float* bias  = (const float*)d_in[18];
    const float* lnw   = (const float*)d_in[19];
    const float* lnb   = (const float*)d_in[20];
    const float* linkW = (const float*)d_in[21];
    const float* linkb = (const float*)d_in[22];
    float* out = (float*)d_out;

    float *p_h384, *p_xl, *p_xr, *p_h2, *p_stats;
    __half* p_hbh;
    cudaGetSymbolAddress((void**)&p_h384, g_h384);
    cudaGetSymbolAddress((void**)&p_xl, g_xl);
    cudaGetSymbolAddress((void**)&p_xr, g_xr);
    cudaGetSymbolAddress((void**)&p_h2, g_h2);
    cudaGetSymbolAddress((void**)&p_hbh, g_hbh);
    cudaGetSymbolAddress((void**)&p_stats, g_stats4);

    const int AGG_BLKS  = (N_NODES * 32 + 255) / 256;
    const int APPLY_BLKS = (N_NODES * 32 + 255) / 256;
    const int PAIR_BLKS = ((N_PAIRS / 2) * 32 + 255) / 256;
    dim3 lgrid(GEMM_BLKS, 2);

    init_kernel<<<SCAN_BLKS, 256>>>();                                        // 1
    fused_embed_count<<<EMBED_BLKS + COUNT_BLKS, 256>>>(x, t, tW, tb, ei, batch); // 2
    scan1_kernel<<<SCAN_BLKS, 256>>>();                                       // 3
    scan2_kernel<<<1, 256>>>();                                               // 4
    scan3_kernel<<<SCAN_BLKS, 256>>>();                                       // 5
    fused_gemm0_scatter<<<2 * GEMM_BLKS + SCAT_BLKS, 256>>>(
        p_h384, W0l, b0l, W0r, b0r, p_xl, p_xr, ei);                          // 6

    // --- layer 0 aggregation ---
    agg_kernel<<<AGG_BLKS, 256>>>(p_xl, p_xr, att0, bias0, batch, p_h2, p_stats);

    // --- layers 1..3: LN fused into GEMM A-load ---
    for (int i = 0; i < 3; i++) {
        const float* Wli = Wl + (size_t)i * 128 * 128;
        const float* bli = bl + (size_t)i * 128;
        const float* Wri = Wr + (size_t)i * 128 * 128;
        const float* bri = br + (size_t)i * 128;
        const float* ai  = att + (size_t)i * 128;
        const float* bi  = bias + (size_t)i * 128;
        const float* st_prev = p_stats + (size_t)i * 2 * N_GRAPHS;
        float* st = p_stats + (size_t)(i + 1) * 2 * N_GRAPHS;
        gemm_tc_ln_kernel<<<lgrid, 256>>>(p_h2, Wli, bli, Wri, bri,
                                          p_xl, p_xr, st_prev, batch,
                                          lnw + (size_t)i * 128, lnb + (size_t)i * 128);
        agg_kernel<<<AGG_BLKS, 256>>>(p_xl, p_xr, ai, bi, batch, p_h2, st);
    }

    // final LN (fp16 output) + pair scoring
    ln_apply_h_kernel<<<APPLY_BLKS, 256>>>(p_h2, batch, lnw + 3 * 128, lnb + 3 * 128,
                                           p_hbh, p_stats + 3 * 2 * N_GRAPHS);
    pair_kernel<<<PAIR_BLKS, 256>>>(p_hbh, pidx, linkW, linkb, out);
    (void)in_sizes; (void)n_in; (void)out_size;
}